// round 15
// baseline (speedup 1.0000x reference)
#include <cuda_runtime.h>
#include <cuda_fp16.h>
#include <math.h>
#include <cstdint>

// Problem constants
#define BSZ    2
#define CDIM   256
#define NDIM   16384      // 128*128
#define HDIM   128
#define WDIM   128
#define NKV    1024       // 32*32
#define NHEADS 8
#define HD     32
#define EPSBN  1e-5f
#define KSR    4096       // CDIM*4*4

typedef unsigned long long u64;
typedef unsigned int u32;
typedef unsigned short u16;

// ===================== mma/ldmatrix helpers (fp16) ============================
__device__ __forceinline__ u32 smem_u32(const void* p) {
    u32 a; asm("{ .reg .u64 t; cvta.to.shared.u64 t, %1; cvt.u32.u64 %0, t; }"
               : "=r"(a) : "l"(p)); return a;
}
__device__ __forceinline__ void ldm_x4(u32 r[4], u32 addr) {
    asm volatile("ldmatrix.sync.aligned.m8n8.x4.shared.b16 {%0,%1,%2,%3}, [%4];"
                 : "=r"(r[0]), "=r"(r[1]), "=r"(r[2]), "=r"(r[3]) : "r"(addr));
}
__device__ __forceinline__ void mma_a(float& c0, float& c1, float& c2, float& c3,
                                      u32 a0, u32 a1, u32 a2, u32 a3,
                                      u32 b0, u32 b1) {
    asm volatile("mma.sync.aligned.m16n8k16.row.col.f32.f16.f16.f32 "
                 "{%0,%1,%2,%3}, {%4,%5,%6,%7}, {%8,%9}, {%0,%1,%2,%3};"
                 : "+f"(c0), "+f"(c1), "+f"(c2), "+f"(c3)
                 : "r"(a0), "r"(a1), "r"(a2), "r"(a3), "r"(b0), "r"(b1));
}
// fp16-accumulator MMA, zero C: output packed half2 x2
__device__ __forceinline__ void mma_h(u32& d0, u32& d1,
                                      u32 a0, u32 a1, u32 a2, u32 a3,
                                      u32 b0, u32 b1) {
    asm volatile("mma.sync.aligned.m16n8k16.row.col.f16.f16.f16.f16 "
                 "{%0,%1}, {%2,%3,%4,%5}, {%6,%7}, {%8,%8};"
                 : "=r"(d0), "=r"(d1)
                 : "r"(a0), "r"(a1), "r"(a2), "r"(a3), "r"(b0), "r"(b1), "r"(0u));
}
__device__ __forceinline__ u32 hadd2u(u32 a, u32 b) {
    u32 d; asm("add.f16x2 %0, %1, %2;" : "=r"(d) : "r"(a), "r"(b)); return d;
}
__device__ __forceinline__ u32 hmax2u(u32 a, u32 b) {
    u32 d; asm("max.f16x2 %0, %1, %2;" : "=r"(d) : "r"(a), "r"(b)); return d;
}
__device__ __forceinline__ u32 sw128(u32 b) { return b ^ ((b >> 3) & 0x70); }

// ===================== fp16 pack helpers ======================================
__device__ __forceinline__ u32 cvt2h(float a, float b) {
    __half2 h = __floats2half2_rn(a, b);
    return *reinterpret_cast<u32*>(&h);
}
__device__ __forceinline__ u64 cvt4h(float4 v) {
    u32 lo = cvt2h(v.x, v.y), hi = cvt2h(v.z, v.w);
    return (u64)lo | ((u64)hi << 32);
}

// ===================== scratch ================================================
__device__ __align__(16) u16  g_qbf [BSZ * NHEADS * NDIM * 32];  // fp16, 64B rows
__device__ __align__(16) u16  g_kbf [BSZ * NHEADS * NKV  * 32];  // fp16, 64B rows
__device__ __align__(16) u16  g_Xt  [BSZ * NDIM * 256];          // fp16 [n][c]
__device__ __align__(16) u16  g_xrT [BSZ * NKV * 256];           // fp16 [m][c]
__device__ __align__(16) u16  g_wqs [CDIM * 256];                // fp16 rows
__device__ __align__(16) u16  g_wks [CDIM * 256];                // fp16 rows
__device__ __align__(16) u16  g_wsrs[CDIM * 4096];               // fp16 [o][(pq)*256+c]
__device__ float g_part[16 * CDIM * NKV];
__device__ float g_attn[2 * BSZ * NHEADS * NDIM];                // [half][bh][n]
__device__ float g_vp  [BSZ * CDIM * 256];
__device__ float g_v   [BSZ * CDIM];
__device__ float g_alpha[BSZ * CDIM];
__device__ float g_bias [CDIM];

// ===================== prep: W fp32 -> fp16 rows ==============================
__global__ __launch_bounds__(256) void convert_w(
    const float* __restrict__ W, u16* __restrict__ out) {
    const int idx = blockIdx.x * 256 + threadIdx.x;
    const int fl = idx * 4;
    float4 v = *(const float4*)&W[fl];
    *(u64*)(out + fl) = cvt4h(v);
}

// ===================== prep: w_sr [o][c][p][q] -> fp16 [o][(p4+q)*256+c] ======
__global__ __launch_bounds__(256) void convert_wsr_perm(
    const float* __restrict__ W, u16* __restrict__ out) {
    __shared__ float s[4096];
    const int o = blockIdx.x;
    const int t = threadIdx.x;
    const float* src = W + (size_t)o * 4096;
    #pragma unroll
    for (int j = 0; j < 4; ++j) {
        float4 v = *(const float4*)&src[t * 16 + j * 4];
        s[t * 16 + j * 4 + 0] = v.x; s[t * 16 + j * 4 + 1] = v.y;
        s[t * 16 + j * 4 + 2] = v.z; s[t * 16 + j * 4 + 3] = v.w;
    }
    __syncthreads();
    const int pq = t >> 4, cg = t & 15;
    u16* dst = out + (size_t)o * 4096 + pq * 256 + cg * 16;
    #pragma unroll
    for (int j = 0; j < 4; ++j) {
        const int c0 = cg * 16 + j * 4;
        float4 v = make_float4(s[(c0 + 0) * 16 + pq], s[(c0 + 1) * 16 + pq],
                               s[(c0 + 2) * 16 + pq], s[(c0 + 3) * 16 + pq]);
        *(u64*)(dst + j * 4) = cvt4h(v);
    }
}

// ===================== prep: x -> Xt (tile transpose -> fp16) + v partials ====
__global__ __launch_bounds__(256) void transpose_split_x(
    const float* __restrict__ x, u16* __restrict__ Xt, float* __restrict__ vp) {
    __shared__ float s[64][65];
    const int n0 = blockIdx.x * 64;
    const int c0 = blockIdx.y * 64;
    const int b  = blockIdx.z;
    const int tid = threadIdx.x;
    #pragma unroll
    for (int i = 0; i < 4; ++i) {
        const int idx = i * 256 + tid;
        const int c_l = idx >> 4, nq = idx & 15;
        float4 v = *(const float4*)&x[((size_t)(b * CDIM + c0 + c_l)) * NDIM + n0 + nq * 4];
        s[c_l][nq * 4 + 0] = v.x; s[c_l][nq * 4 + 1] = v.y;
        s[c_l][nq * 4 + 2] = v.z; s[c_l][nq * 4 + 3] = v.w;
    }
    __syncthreads();
    const int n_l = tid >> 2, cq = tid & 3;
    u16* orow = Xt + ((size_t)(b * NDIM + n0 + n_l)) * 256 + c0;
    #pragma unroll
    for (int i = 0; i < 4; ++i) {
        const int c_loc = (cq + i * 4) * 4;
        float4 v = make_float4(s[c_loc][n_l], s[c_loc + 1][n_l],
                               s[c_loc + 2][n_l], s[c_loc + 3][n_l]);
        *(u64*)(orow + c_loc) = cvt4h(v);
    }
    if (tid < 64) {
        float acc = 0.f;
        #pragma unroll 16
        for (int n = 0; n < 64; ++n) acc += s[tid][n];
        vp[((size_t)(b * CDIM + c0 + tid)) * 256 + blockIdx.x] = acc;
    }
}

// ---------------- v = mean (reduce partials) ----------------------------------
__global__ __launch_bounds__(256) void vp_reduce(const float* __restrict__ vp,
                                                 float* __restrict__ v) {
    const int bc = blockIdx.x;
    __shared__ float red[256];
    red[threadIdx.x] = vp[(size_t)bc * 256 + threadIdx.x];
    __syncthreads();
    for (int st = 128; st > 0; st >>= 1) {
        if (threadIdx.x < st) red[threadIdx.x] += red[threadIdx.x + st];
        __syncthreads();
    }
    if (threadIdx.x == 0) v[bc] = red[0] * (1.0f / NDIM);
}

// ===================== generic GEMM on mma.sync (M rows @ [row][256] fp16) ====
__global__ __launch_bounds__(256, 2) void qgemm_mma(
    const u16* __restrict__ Xt, const u16* __restrict__ Wq,
    u16* __restrict__ qbf, int Ncol) {
    extern __shared__ char sm[];
    const u32 sb = smem_u32(sm);
    const int tid = threadIdx.x;
    const int l = tid & 31, wid = tid >> 5;
    const int wm = wid & 3, wo = wid >> 2;
    const int blkn = blockIdx.x, blko = blockIdx.y, bb = blockIdx.z;

    const u16* XtB = Xt + ((size_t)bb * Ncol + blkn * 128) * 256;
    const u16* WqB = Wq + (size_t)(blko * 128) * 256;

    float acc[2][8][4];
    #pragma unroll
    for (int a = 0; a < 2; ++a)
        #pragma unroll
        for (int c = 0; c < 8; ++c)
            #pragma unroll
            for (int d = 0; d < 4; ++d) acc[a][c][d] = 0.f;

    u32 rowA[2], rowB[4];
    #pragma unroll
    for (int mt = 0; mt < 2; ++mt)
        rowA[mt] = (u32)(wm * 32 + mt * 16 + (l & 7) + (l & 8)) * 128;
    #pragma unroll
    for (int g = 0; g < 4; ++g)
        rowB[g] = (u32)(wo * 64 + g * 16 + (l & 7) + ((l & 16) >> 1)) * 128;

    for (int kc = 0; kc < 4; ++kc) {
        for (int i = tid; i < 1024; i += 256) {
            const int row = i >> 3, ch = i & 7;
            const u32 dst = sw128((u32)(row * 128 + ch * 16));
            const size_t off = (size_t)row * 256 + kc * 64 + ch * 8;
            *(uint4*)(sm + dst)         = *(const uint4*)(XtB + off);
            *(uint4*)(sm + 16384 + dst) = *(const uint4*)(WqB + off);
        }
        __syncthreads();
        #pragma unroll
        for (int s = 0; s < 4; ++s) {
            const u32 cA = ((u32)((2 * s + ((l >> 4) & 1)) ^ (l & 7))) << 4;
            const u32 cB = ((u32)((2 * s + ((l >> 3) & 1)) ^ (l & 7))) << 4;
            u32 a[2][4], bf[4][4];
            #pragma unroll
            for (int mt = 0; mt < 2; ++mt)
                ldm_x4(a[mt], sb + rowA[mt] + cA);
            #pragma unroll
            for (int g = 0; g < 4; ++g)
                ldm_x4(bf[g], sb + 16384 + rowB[g] + cB);
            #pragma unroll
            for (int mt = 0; mt < 2; ++mt)
                #pragma unroll
                for (int g = 0; g < 4; ++g)
                    #pragma unroll
                    for (int hf = 0; hf < 2; ++hf) {
                        float* A4 = acc[mt][g * 2 + hf];
                        mma_a(A4[0], A4[1], A4[2], A4[3],
                              a[mt][0], a[mt][1], a[mt][2], a[mt][3],
                              bf[g][2 * hf], bf[g][2 * hf + 1]);
                    }
        }
        __syncthreads();
    }

    #pragma unroll
    for (int mt = 0; mt < 2; ++mt) {
        const int n0g = blkn * 128 + wm * 32 + mt * 16 + (l >> 2);
        #pragma unroll
        for (int nt = 0; nt < 8; ++nt) {
            const int o = blko * 128 + wo * 64 + nt * 8 + 2 * (l & 3);
            const int bh_ = bb * NHEADS + (o >> 5);
            const int d = o & 31;
            u16* base = qbf + ((size_t)bh_ * Ncol + n0g) * 32 + d;
            *(u32*)base = cvt2h(acc[mt][nt][0], acc[mt][nt][1]);
            *(u32*)(base + 8 * 32) = cvt2h(acc[mt][nt][2], acc[mt][nt][3]);
        }
    }
}

// ===================== conv GEMM: B gathered from Xt, K order (p,q,c) =========
__global__ __launch_bounds__(256, 2) void convgemm_mma(
    const u16* __restrict__ Wsr, const u16* __restrict__ Xt,
    float* __restrict__ part) {
    extern __shared__ char sm[];
    const u32 sb = smem_u32(sm);
    const int tid = threadIdx.x;
    const int l = tid & 31, wid = tid >> 5;
    const int wm = wid & 3, wo = wid >> 2;
    const int blkm = blockIdx.x, blko = blockIdx.y;
    const int zz = blockIdx.z;
    const int bb = zz & 1, ks = zz >> 1;

    const u16* AB  = Wsr + (size_t)(blko * 128) * 4096;
    const u16* XtB = Xt + (size_t)bb * NDIM * 256;

    float acc[2][8][4];
    #pragma unroll
    for (int a = 0; a < 2; ++a)
        #pragma unroll
        for (int c = 0; c < 8; ++c)
            #pragma unroll
            for (int d = 0; d < 4; ++d) acc[a][c][d] = 0.f;

    u32 rowA[2], rowB[4];
    #pragma unroll
    for (int mt = 0; mt < 2; ++mt)
        rowA[mt] = (u32)(wm * 32 + mt * 16 + (l & 7) + (l & 8)) * 128;
    #pragma unroll
    for (int g = 0; g < 4; ++g)
        rowB[g] = (u32)(wo * 64 + g * 16 + (l & 7) + ((l & 16) >> 1)) * 128;

    for (int kcl = 0; kcl < 8; ++kcl) {
        const int kcg = ks * 8 + kcl;
        const int sect = kcg >> 2;
        const int p = sect >> 2, qq = sect & 3;
        const int ccol = (kcg & 3) * 64;
        for (int i = tid; i < 1024; i += 256) {
            const int row = i >> 3, ch = i & 7;
            const u32 dst = sw128((u32)(row * 128 + ch * 16));
            *(uint4*)(sm + dst) = *(const uint4*)(AB + (size_t)row * 4096 + kcg * 64 + ch * 8);
            const int m = blkm * 128 + row;
            const int hh = m >> 5, ww = m & 31;
            const int n = (hh * 4 + p) * WDIM + ww * 4 + qq;
            *(uint4*)(sm + 16384 + dst) = *(const uint4*)(XtB + (size_t)n * 256 + ccol + ch * 8);
        }
        __syncthreads();
        #pragma unroll
        for (int s = 0; s < 4; ++s) {
            const u32 cA = ((u32)((2 * s + ((l >> 4) & 1)) ^ (l & 7))) << 4;
            const u32 cB = ((u32)((2 * s + ((l >> 3) & 1)) ^ (l & 7))) << 4;
            u32 a[2][4], bf[4][4];
            #pragma unroll
            for (int mt = 0; mt < 2; ++mt)
                ldm_x4(a[mt], sb + rowA[mt] + cA);
            #pragma unroll
            for (int g = 0; g < 4; ++g)
                ldm_x4(bf[g], sb + 16384 + rowB[g] + cB);
            #pragma unroll
            for (int mt = 0; mt < 2; ++mt)
                #pragma unroll
                for (int g = 0; g < 4; ++g)
                    #pragma unroll
                    for (int hf = 0; hf < 2; ++hf) {
                        float* A4 = acc[mt][g * 2 + hf];
                        mma_a(A4[0], A4[1], A4[2], A4[3],
                              a[mt][0], a[mt][1], a[mt][2], a[mt][3],
                              bf[g][2 * hf], bf[g][2 * hf + 1]);
                    }
        }
        __syncthreads();
    }

    #pragma unroll
    for (int mt = 0; mt < 2; ++mt) {
        const int o = blko * 128 + wm * 32 + mt * 16 + (l >> 2);
        #pragma unroll
        for (int nt = 0; nt < 8; ++nt) {
            const int m = blkm * 128 + wo * 64 + nt * 8 + 2 * (l & 3);
            float* dst = part + ((size_t)zz * CDIM + o) * NKV + m;
            *(float2*)dst = make_float2(acc[mt][nt][0], acc[mt][nt][1]);
            *(float2*)(dst + 8 * NKV) = make_float2(acc[mt][nt][2], acc[mt][nt][3]);
        }
    }
}

// ===================== conv reduce + BN + transpose -> xrT fp16 ===============
__global__ __launch_bounds__(256) void conv_reduce_bn_T(
    const float* __restrict__ part,
    const float* __restrict__ gam, const float* __restrict__ bet,
    const float* __restrict__ mu,  const float* __restrict__ var,
    u16* __restrict__ xrT) {
    __shared__ float s[64][65];
    const int m0 = blockIdx.x * 64;
    const int o0 = blockIdx.y * 64;
    const int b  = blockIdx.z;
    const int tid = threadIdx.x;
    const int o_l0 = tid >> 4, m4 = (tid & 15) * 4;
    #pragma unroll
    for (int i = 0; i < 4; ++i) {
        const int o_l = o_l0 + i * 16;
        const int o = o0 + o_l;
        float4 sum = make_float4(0.f, 0.f, 0.f, 0.f);
        #pragma unroll
        for (int ks = 0; ks < 8; ++ks) {
            const float4 p = *(const float4*)&part[((size_t)(ks * 2 + b) * CDIM + o) * NKV + m0 + m4];
            sum.x += p.x; sum.y += p.y; sum.z += p.z; sum.w += p.w;
        }
        const float inv = gam[o] * rsqrtf(var[o] + EPSBN);
        const float mb = mu[o], be = bet[o];
        s[o_l][m4 + 0] = (sum.x - mb) * inv + be;
        s[o_l][m4 + 1] = (sum.y - mb) * inv + be;
        s[o_l][m4 + 2] = (sum.z - mb) * inv + be;
        s[o_l][m4 + 3] = (sum.w - mb) * inv + be;
    }
    __syncthreads();
    const int m_l = tid >> 2, cq = tid & 3;
    u16* orow = xrT + ((size_t)(b * NKV + m0 + m_l)) * 256 + o0;
    #pragma unroll
    for (int j = 0; j < 4; ++j) {
        const int c0 = (cq + j * 4) * 4;
        float4 v = make_float4(s[c0][m_l], s[c0 + 1][m_l],
                               s[c0 + 2][m_l], s[c0 + 3][m_l]);
        *(u64*)(orow + c0) = cvt4h(v);
    }
}

// ---------------- alpha/bias --------------------------------------------------
__global__ __launch_bounds__(256) void alpha_kernel(
    const float* __restrict__ wproj, const float* __restrict__ v,
    const float* __restrict__ gam, const float* __restrict__ bet,
    const float* __restrict__ mu,  const float* __restrict__ var,
    float* __restrict__ alpha, float* __restrict__ bias) {
    const int b = blockIdx.x;
    const int o = threadIdx.x;
    __shared__ float vs[CDIM];
    vs[o] = v[b * CDIM + o];
    __syncthreads();
    float p = 0.f;
    const float* wr = wproj + (size_t)o * CDIM;
    #pragma unroll 8
    for (int c = 0; c < CDIM; ++c) p = fmaf(wr[c], vs[c], p);
    const float inv = gam[o] * rsqrtf(var[o] + EPSBN);
    alpha[b * CDIM + o] = p * inv;
    if (b == 0) bias[o] = bet[o] - mu[o] * inv;
}

// ===================== fp16 mma.sync attention (f16 accum, kv-split) ==========
#define SM_QOFF 32768
#define SM_TOT  40960
#define NTILES  16

__global__ __launch_bounds__(256, 2)
void attn_mma(const u16* __restrict__ qbf, const u16* __restrict__ kbf,
              float* __restrict__ attn) {
    extern __shared__ char smem[];
    const u32 sb  = smem_u32(smem);
    const int tid = threadIdx.x;
    const int wid = tid >> 5, l = tid & 31;
    const int seg  = blockIdx.x;
    const int half = blockIdx.y;
    const int bh   = blockIdx.z;

    {
        const uint4* ksrc = (const uint4*)(kbf + (size_t)(bh * NKV + half * 512) * 32);
        for (int idx = tid; idx < 512 * 4; idx += 256) {
            const int row = idx >> 2, c = idx & 3;
            const u32 off = (u32)((row >> 1) * 128 + (row & 1) * 64 + c * 16);
            *(uint4*)(smem + sw128(off)) = ksrc[idx];
        }
    }
    __syncthreads();

    const int brow = (l & 7) + ((l & 16) >> 1);
    u32 baddr[2];
    #pragma unroll
    for (int s = 0; s < 2; ++s) {
        const u32 off = (u32)((brow >> 1) * 128 + (brow & 1) * 64
                              + (2 * s + ((l >> 3) & 1)) * 16);
        baddr[s] = sb + sw128(off);
    }
    const int Rr = wid * 16 + (l & 15);
    u32 aaddr[2];
    #pragma unroll
    for (int s = 0; s < 2; ++s) {
        const u32 off = (u32)((Rr >> 1) * 128 + (Rr & 1) * 64 + (2 * s + (l >> 4)) * 16);
        aaddr[s] = sb + SM_QOFF + sw128(off);
    }

    const float scale = 0.17677669529663687f;
    float* ob = attn + ((size_t)(half * 16 + bh)) * NDIM;
    const u32 NEGINF2 = 0xFC00FC00u;

    for (int t = 0; t < NTILES; ++t) {
        const int n_base = (seg * NTILES + t) * 128;
        {
            const uint4* qsrc = (const uint4*)(qbf + ((size_t)bh * NDIM + n_base) * 32);
            const int row = tid >> 1;
            const int c0 = (tid & 1) * 2;
            #pragma unroll
            for (int j = 0; j < 2; ++j) {
                const int c = c0 + j;
                const u32 off = (u32)((row >> 1) * 128 + (row & 1) * 64 + c * 16);
                *(uint4*)(smem + SM_QOFF + sw128(off)) = qsrc[(size_t)row * 4 + c];
            }
        }
        __syncwarp();

        u32 a[2][4];
        ldm_x4(a[0], aaddr[0]);
        ldm_x4(a[1], aaddr[1]);
        __syncwarp();

        u32 rm0 = NEGINF2, rm1 = NEGINF2;
        #pragma unroll 4
        for (int kv = 0; kv < 32; ++kv) {
            const u32 off = (u32)kv * 1024;
            u32 b0[4], b1[4];
            ldm_x4(b0, baddr[0] + off);
            ldm_x4(b1, baddr[1] + off);
            #pragma unroll
            for (int g = 0; g < 2; ++g) {
                u32 A0, A1, B0, B1;
                mma_h(A0, A1, a[0][0], a[0][1], a[0][2], a[0][3],
                      b0[2 * g], b0[2 * g + 1]);
                mma_h(B0, B1, a[1][0], a[1][1], a[1][2], a[1][3],
                      b1[2 * g], b1[2 * g + 1]);
                rm0 = hmax2u(rm0, hadd2u(A0, B0));
                rm1 = hmax2u(rm1, hadd2u(A1, B1));
            }
        }
        __half2 h0 = *reinterpret_cast<__half2*>(&rm0);
        __half2 h1 = *reinterpret_cast<__half2*>(&rm1);
        float rmax[2];
        rmax[0] = fmaxf(__half2float(__low2half(h0)), __half2float(__high2half(h0)));
        rmax[1] = fmaxf(__half2float(__low2half(h1)), __half2float(__high2half(h1)));
        #pragma unroll
        for (int rr = 0; rr < 2; ++rr) {
            float v = rmax[rr];
            v = fmaxf(v, __shfl_xor_sync(0xffffffffu, v, 1));
            v = fmaxf(v, __shfl_xor_sync(0xffffffffu, v, 2));
            rmax[rr] = v;
        }
        if ((l & 3) == 0) {
            const int rbase = n_base + wid * 16;
            ob[rbase + (l >> 2) + 0] = rmax[0] * scale;
            ob[rbase + (l >> 2) + 8] = rmax[1] * scale;
        }
        __syncwarp();
    }
}

// ---------------- fused tail: S = sum_h max(halves); out = alpha*S + bias -----
// grid (64 n-chunks, 2 b); 256 threads; each block: 256 n x all 256 o.
__global__ __launch_bounds__(256) void fused_tail(
    const float* __restrict__ attn, const float* __restrict__ alpha,
    const float* __restrict__ bias, float* __restrict__ out) {
    __shared__ float Ssh[256];
    __shared__ float ash[256], bsh[256];
    const int n0 = blockIdx.x * 256;
    const int b  = blockIdx.y;
    const int tid = threadIdx.x;
    // S for this n-chunk
    {
        const int n = n0 + tid;
        float s = 0.f;
        #pragma unroll
        for (int h = 0; h < NHEADS; ++h) {
            const size_t base = ((size_t)(b * NHEADS + h)) * NDIM + n;
            s += fmaxf(attn[base], attn[base + (size_t)16 * NDIM]);
        }
        Ssh[tid] = s;
        ash[tid] = alpha[b * CDIM + tid];
        bsh[tid] = bias[tid];
    }
    __syncthreads();
    // write 256 o rows x 256 n: thread handles 4 consecutive n per (o, iter)
    const int nq = (tid & 63) * 4;     // n offset within chunk
    const int o0 = tid >> 6;           // 0..3
    float4 s4 = *(const float4*)&Ssh[nq];
    #pragma unroll
    for (int i = 0; i < 64; ++i) {
        const int o = o0 + i * 4;
        const float a = ash[o], bi = bsh[o];
        float4 r;
        r.x = fmaf(a, s4.x, bi); r.y = fmaf(a, s4.y, bi);
        r.z = fmaf(a, s4.z, bi); r.w = fmaf(a, s4.w, bi);
        *(float4*)&out[((size_t)(b * CDIM + o)) * NDIM + n0 + nq] = r;
    }
}

// ===================== launch (stream-forked for graph overlap) ================
extern "C" void kernel_launch(void* const* d_in, const int* in_sizes, int n_in,
                              void* d_out, int out_size) {
    const float* x      = (const float*)d_in[0];
    const float* w_q    = (const float*)d_in[1];
    const float* w_k    = (const float*)d_in[2];
    const float* w_sr   = (const float*)d_in[3];
    const float* sr_g   = (const float*)d_in[4];
    const float* sr_b   = (const float*)d_in[5];
    const float* sr_m   = (const float*)d_in[6];
    const float* sr_v   = (const float*)d_in[7];
    const float* w_proj = (const float*)d_in[8];
    const float* pj_g   = (const float*)d_in[9];
    const float* pj_b   = (const float*)d_in[10];
    const float* pj_m   = (const float*)d_in[11];
    const float* pj_v   = (const float*)d_in[12];
    float* out = (float*)d_out;

    u16 *qbf, *kbf, *Xt, *xrT, *wqs, *wks, *wsrs;
    float *part, *attn, *vp, *v, *alpha, *bias;
    cudaGetSymbolAddress((void**)&qbf,   g_qbf);
    cudaGetSymbolAddress((void**)&kbf,   g_kbf);
    cudaGetSymbolAddress((void**)&Xt,    g_Xt);
    cudaGetSymbolAddress((void**)&xrT,   g_xrT);
    cudaGetSymbolAddress((void**)&wqs,   g_wqs);
    cudaGetSymbolAddress((void**)&wks,   g_wks);
    cudaGetSymbolAddress((void**)&wsrs,  g_wsrs);
    cudaGetSymbolAddress((void**)&part,  g_part);
    cudaGetSymbolAddress((void**)&attn,  g_attn);
    cudaGetSymbolAddress((void**)&vp,    g_vp);
    cudaGetSymbolAddress((void**)&v,     g_v);
    cudaGetSymbolAddress((void**)&alpha, g_alpha);
    cudaGetSymbolAddress((void**)&bias,  g_bias);

    cudaFuncSetAttribute(attn_mma, cudaFuncAttributeMaxDynamicSharedMemorySize, SM_TOT);
    cudaFuncSetAttribute(qgemm_mma, cudaFuncAttributeMaxDynamicSharedMemorySize, 32768);
    cudaFuncSetAttribute(convgemm_mma, cudaFuncAttributeMaxDynamicSharedMemorySize, 32768);

    cudaStream_t s1;
    cudaStreamCreateWithFlags(&s1, cudaStreamNonBlocking);
    cudaEvent_t eFork, eW, eX, eJoin;
    cudaEventCreateWithFlags(&eFork, cudaEventDisableTiming);
    cudaEventCreateWithFlags(&eW, cudaEventDisableTiming);
    cudaEventCreateWithFlags(&eX, cudaEventDisableTiming);
    cudaEventCreateWithFlags(&eJoin, cudaEventDisableTiming);

    cudaEventRecord(eFork, 0);
    cudaStreamWaitEvent(s1, eFork, 0);

    // ---- s1: weight converts (concurrent with transpose) ----
    convert_w<<<64, 256, 0, s1>>>(w_q, wqs);
    convert_w<<<64, 256, 0, s1>>>(w_k, wks);
    convert_wsr_perm<<<256, 256, 0, s1>>>(w_sr, wsrs);
    cudaEventRecord(eW, s1);

    // ---- main: the single x pass ----
    transpose_split_x<<<dim3(256, 4, 2), 256>>>(x, Xt, vp);
    cudaEventRecord(eX, 0);
    cudaStreamWaitEvent(0, eW, 0);     // main (kv-chain) needs wsrs/wks
    cudaStreamWaitEvent(s1, eX, 0);    // s1 (q-chain) needs Xt

    // ---- s1: q-chain + v/alpha ----
    qgemm_mma<<<dim3(128, 2, 2), 256, 32768, s1>>>(Xt, wqs, qbf, NDIM);
    vp_reduce<<<BSZ * CDIM, 256, 0, s1>>>(vp, v);
    alpha_kernel<<<BSZ, CDIM, 0, s1>>>(w_proj, v, pj_g, pj_b, pj_m, pj_v, alpha, bias);
    cudaEventRecord(eJoin, s1);

    // ---- main: kv-chain ----
    convgemm_mma<<<dim3(8, 2, 16), 256, 32768>>>(wsrs, Xt, part);
    conv_reduce_bn_T<<<dim3(16, 4, 2), 256>>>(part, sr_g, sr_b, sr_m, sr_v, xrT);
    qgemm_mma<<<dim3(8, 2, 2), 256, 32768>>>(xrT, wks, kbf, NKV);   // k GEMM

    // ---- join, then attention + fused tail ----
    cudaStreamWaitEvent(0, eJoin, 0);
    attn_mma<<<dim3(8, 2, 16), 256, SM_TOT>>>(qbf, kbf, attn);
    fused_tail<<<dim3(64, 2), 256>>>(attn, alpha, bias, out);
}

// round 16
// speedup vs baseline: 1.0023x; 1.0023x over previous
#include <cuda_runtime.h>
#include <cuda_fp16.h>
#include <math.h>
#include <cstdint>

// Problem constants
#define BSZ    2
#define CDIM   256
#define NDIM   16384      // 128*128
#define HDIM   128
#define WDIM   128
#define NKV    1024       // 32*32
#define NHEADS 8
#define HD     32
#define EPSBN  1e-5f
#define KSR    4096       // CDIM*4*4

typedef unsigned long long u64;
typedef unsigned int u32;
typedef unsigned short u16;

// ===================== mma/ldmatrix helpers (fp16) ============================
__device__ __forceinline__ u32 smem_u32(const void* p) {
    u32 a; asm("{ .reg .u64 t; cvta.to.shared.u64 t, %1; cvt.u32.u64 %0, t; }"
               : "=r"(a) : "l"(p)); return a;
}
__device__ __forceinline__ void ldm_x4(u32 r[4], u32 addr) {
    asm volatile("ldmatrix.sync.aligned.m8n8.x4.shared.b16 {%0,%1,%2,%3}, [%4];"
                 : "=r"(r[0]), "=r"(r[1]), "=r"(r[2]), "=r"(r[3]) : "r"(addr));
}
__device__ __forceinline__ void mma_a(float& c0, float& c1, float& c2, float& c3,
                                      u32 a0, u32 a1, u32 a2, u32 a3,
                                      u32 b0, u32 b1) {
    asm volatile("mma.sync.aligned.m16n8k16.row.col.f32.f16.f16.f32 "
                 "{%0,%1,%2,%3}, {%4,%5,%6,%7}, {%8,%9}, {%0,%1,%2,%3};"
                 : "+f"(c0), "+f"(c1), "+f"(c2), "+f"(c3)
                 : "r"(a0), "r"(a1), "r"(a2), "r"(a3), "r"(b0), "r"(b1));
}
// fp16-accumulator MMA, zero C: output packed half2 x2
__device__ __forceinline__ void mma_h(u32& d0, u32& d1,
                                      u32 a0, u32 a1, u32 a2, u32 a3,
                                      u32 b0, u32 b1) {
    asm volatile("mma.sync.aligned.m16n8k16.row.col.f16.f16.f16.f16 "
                 "{%0,%1}, {%2,%3,%4,%5}, {%6,%7}, {%8,%8};"
                 : "=r"(d0), "=r"(d1)
                 : "r"(a0), "r"(a1), "r"(a2), "r"(a3), "r"(b0), "r"(b1), "r"(0u));
}
__device__ __forceinline__ u32 hadd2u(u32 a, u32 b) {
    u32 d; asm("add.f16x2 %0, %1, %2;" : "=r"(d) : "r"(a), "r"(b)); return d;
}
__device__ __forceinline__ u32 hmax2u(u32 a, u32 b) {
    u32 d; asm("max.f16x2 %0, %1, %2;" : "=r"(d) : "r"(a), "r"(b)); return d;
}
__device__ __forceinline__ u32 sw128(u32 b) { return b ^ ((b >> 3) & 0x70); }

// ===================== fp16 pack helpers ======================================
__device__ __forceinline__ u32 cvt2h(float a, float b) {
    __half2 h = __floats2half2_rn(a, b);
    return *reinterpret_cast<u32*>(&h);
}
__device__ __forceinline__ u64 cvt4h(float4 v) {
    u32 lo = cvt2h(v.x, v.y), hi = cvt2h(v.z, v.w);
    return (u64)lo | ((u64)hi << 32);
}

// ===================== scratch ================================================
__device__ __align__(16) u16  g_qbf [BSZ * NHEADS * NDIM * 32];  // fp16, 64B rows
__device__ __align__(16) u16  g_kbf [BSZ * NHEADS * NKV  * 32];  // fp16, 64B rows
__device__ __align__(16) u16  g_Xt  [BSZ * NDIM * 256];          // fp16 [n][c]
__device__ __align__(16) u16  g_xrT [BSZ * NKV * 256];           // fp16 [m][c]
__device__ __align__(16) u16  g_wqs [CDIM * 256];                // fp16 rows
__device__ __align__(16) u16  g_wks [CDIM * 256];                // fp16 rows
__device__ __align__(16) u16  g_wsrs[CDIM * 4096];               // fp16 [o][(pq)*256+c]
__device__ float g_part[16 * CDIM * NKV];
__device__ float g_attn[2 * BSZ * NHEADS * NDIM];                // [half][bh][n]
__device__ float g_vp  [BSZ * CDIM * 256];
__device__ float g_v   [BSZ * CDIM];
__device__ float g_alpha[BSZ * CDIM];
__device__ float g_bias [CDIM];

// ===================== prep: W fp32 -> fp16 rows ==============================
__global__ __launch_bounds__(256) void convert_w(
    const float* __restrict__ W, u16* __restrict__ out) {
    const int idx = blockIdx.x * 256 + threadIdx.x;
    const int fl = idx * 4;
    float4 v = *(const float4*)&W[fl];
    *(u64*)(out + fl) = cvt4h(v);
}

// ===================== prep: w_sr [o][c][p][q] -> fp16 [o][(p4+q)*256+c] ======
__global__ __launch_bounds__(256) void convert_wsr_perm(
    const float* __restrict__ W, u16* __restrict__ out) {
    __shared__ float s[4096];
    const int o = blockIdx.x;
    const int t = threadIdx.x;
    const float* src = W + (size_t)o * 4096;
    #pragma unroll
    for (int j = 0; j < 4; ++j) {
        float4 v = *(const float4*)&src[t * 16 + j * 4];
        s[t * 16 + j * 4 + 0] = v.x; s[t * 16 + j * 4 + 1] = v.y;
        s[t * 16 + j * 4 + 2] = v.z; s[t * 16 + j * 4 + 3] = v.w;
    }
    __syncthreads();
    const int pq = t >> 4, cg = t & 15;
    u16* dst = out + (size_t)o * 4096 + pq * 256 + cg * 16;
    #pragma unroll
    for (int j = 0; j < 4; ++j) {
        const int c0 = cg * 16 + j * 4;
        float4 v = make_float4(s[(c0 + 0) * 16 + pq], s[(c0 + 1) * 16 + pq],
                               s[(c0 + 2) * 16 + pq], s[(c0 + 3) * 16 + pq]);
        *(u64*)(dst + j * 4) = cvt4h(v);
    }
}

// ===================== prep: x -> Xt (tile transpose -> fp16) + v partials ====
__global__ __launch_bounds__(256) void transpose_split_x(
    const float* __restrict__ x, u16* __restrict__ Xt, float* __restrict__ vp) {
    __shared__ float s[64][65];
    const int n0 = blockIdx.x * 64;
    const int c0 = blockIdx.y * 64;
    const int b  = blockIdx.z;
    const int tid = threadIdx.x;
    #pragma unroll
    for (int i = 0; i < 4; ++i) {
        const int idx = i * 256 + tid;
        const int c_l = idx >> 4, nq = idx & 15;
        float4 v = *(const float4*)&x[((size_t)(b * CDIM + c0 + c_l)) * NDIM + n0 + nq * 4];
        s[c_l][nq * 4 + 0] = v.x; s[c_l][nq * 4 + 1] = v.y;
        s[c_l][nq * 4 + 2] = v.z; s[c_l][nq * 4 + 3] = v.w;
    }
    __syncthreads();
    const int n_l = tid >> 2, cq = tid & 3;
    u16* orow = Xt + ((size_t)(b * NDIM + n0 + n_l)) * 256 + c0;
    #pragma unroll
    for (int i = 0; i < 4; ++i) {
        const int c_loc = (cq + i * 4) * 4;
        float4 v = make_float4(s[c_loc][n_l], s[c_loc + 1][n_l],
                               s[c_loc + 2][n_l], s[c_loc + 3][n_l]);
        *(u64*)(orow + c_loc) = cvt4h(v);
    }
    if (tid < 64) {
        float acc = 0.f;
        #pragma unroll 16
        for (int n = 0; n < 64; ++n) acc += s[tid][n];
        vp[((size_t)(b * CDIM + c0 + tid)) * 256 + blockIdx.x] = acc;
    }
}

// ---------------- v = mean (reduce partials) ----------------------------------
__global__ __launch_bounds__(256) void vp_reduce(const float* __restrict__ vp,
                                                 float* __restrict__ v) {
    const int bc = blockIdx.x;
    __shared__ float red[256];
    red[threadIdx.x] = vp[(size_t)bc * 256 + threadIdx.x];
    __syncthreads();
    for (int st = 128; st > 0; st >>= 1) {
        if (threadIdx.x < st) red[threadIdx.x] += red[threadIdx.x + st];
        __syncthreads();
    }
    if (threadIdx.x == 0) v[bc] = red[0] * (1.0f / NDIM);
}

// ===================== generic GEMM on mma.sync (M rows @ [row][256] fp16) ====
__global__ __launch_bounds__(256, 2) void qgemm_mma(
    const u16* __restrict__ Xt, const u16* __restrict__ Wq,
    u16* __restrict__ qbf, int Ncol) {
    extern __shared__ char sm[];
    const u32 sb = smem_u32(sm);
    const int tid = threadIdx.x;
    const int l = tid & 31, wid = tid >> 5;
    const int wm = wid & 3, wo = wid >> 2;
    const int blkn = blockIdx.x, blko = blockIdx.y, bb = blockIdx.z;

    const u16* XtB = Xt + ((size_t)bb * Ncol + blkn * 128) * 256;
    const u16* WqB = Wq + (size_t)(blko * 128) * 256;

    float acc[2][8][4];
    #pragma unroll
    for (int a = 0; a < 2; ++a)
        #pragma unroll
        for (int c = 0; c < 8; ++c)
            #pragma unroll
            for (int d = 0; d < 4; ++d) acc[a][c][d] = 0.f;

    u32 rowA[2], rowB[4];
    #pragma unroll
    for (int mt = 0; mt < 2; ++mt)
        rowA[mt] = (u32)(wm * 32 + mt * 16 + (l & 7) + (l & 8)) * 128;
    #pragma unroll
    for (int g = 0; g < 4; ++g)
        rowB[g] = (u32)(wo * 64 + g * 16 + (l & 7) + ((l & 16) >> 1)) * 128;

    for (int kc = 0; kc < 4; ++kc) {
        for (int i = tid; i < 1024; i += 256) {
            const int row = i >> 3, ch = i & 7;
            const u32 dst = sw128((u32)(row * 128 + ch * 16));
            const size_t off = (size_t)row * 256 + kc * 64 + ch * 8;
            *(uint4*)(sm + dst)         = *(const uint4*)(XtB + off);
            *(uint4*)(sm + 16384 + dst) = *(const uint4*)(WqB + off);
        }
        __syncthreads();
        #pragma unroll
        for (int s = 0; s < 4; ++s) {
            const u32 cA = ((u32)((2 * s + ((l >> 4) & 1)) ^ (l & 7))) << 4;
            const u32 cB = ((u32)((2 * s + ((l >> 3) & 1)) ^ (l & 7))) << 4;
            u32 a[2][4], bf[4][4];
            #pragma unroll
            for (int mt = 0; mt < 2; ++mt)
                ldm_x4(a[mt], sb + rowA[mt] + cA);
            #pragma unroll
            for (int g = 0; g < 4; ++g)
                ldm_x4(bf[g], sb + 16384 + rowB[g] + cB);
            #pragma unroll
            for (int mt = 0; mt < 2; ++mt)
                #pragma unroll
                for (int g = 0; g < 4; ++g)
                    #pragma unroll
                    for (int hf = 0; hf < 2; ++hf) {
                        float* A4 = acc[mt][g * 2 + hf];
                        mma_a(A4[0], A4[1], A4[2], A4[3],
                              a[mt][0], a[mt][1], a[mt][2], a[mt][3],
                              bf[g][2 * hf], bf[g][2 * hf + 1]);
                    }
        }
        __syncthreads();
    }

    #pragma unroll
    for (int mt = 0; mt < 2; ++mt) {
        const int n0g = blkn * 128 + wm * 32 + mt * 16 + (l >> 2);
        #pragma unroll
        for (int nt = 0; nt < 8; ++nt) {
            const int o = blko * 128 + wo * 64 + nt * 8 + 2 * (l & 3);
            const int bh_ = bb * NHEADS + (o >> 5);
            const int d = o & 31;
            u16* base = qbf + ((size_t)bh_ * Ncol + n0g) * 32 + d;
            *(u32*)base = cvt2h(acc[mt][nt][0], acc[mt][nt][1]);
            *(u32*)(base + 8 * 32) = cvt2h(acc[mt][nt][2], acc[mt][nt][3]);
        }
    }
}

// ===================== conv GEMM: B gathered from Xt, K order (p,q,c) =========
__global__ __launch_bounds__(256, 2) void convgemm_mma(
    const u16* __restrict__ Wsr, const u16* __restrict__ Xt,
    float* __restrict__ part) {
    extern __shared__ char sm[];
    const u32 sb = smem_u32(sm);
    const int tid = threadIdx.x;
    const int l = tid & 31, wid = tid >> 5;
    const int wm = wid & 3, wo = wid >> 2;
    const int blkm = blockIdx.x, blko = blockIdx.y;
    const int zz = blockIdx.z;
    const int bb = zz & 1, ks = zz >> 1;

    const u16* AB  = Wsr + (size_t)(blko * 128) * 4096;
    const u16* XtB = Xt + (size_t)bb * NDIM * 256;

    float acc[2][8][4];
    #pragma unroll
    for (int a = 0; a < 2; ++a)
        #pragma unroll
        for (int c = 0; c < 8; ++c)
            #pragma unroll
            for (int d = 0; d < 4; ++d) acc[a][c][d] = 0.f;

    u32 rowA[2], rowB[4];
    #pragma unroll
    for (int mt = 0; mt < 2; ++mt)
        rowA[mt] = (u32)(wm * 32 + mt * 16 + (l & 7) + (l & 8)) * 128;
    #pragma unroll
    for (int g = 0; g < 4; ++g)
        rowB[g] = (u32)(wo * 64 + g * 16 + (l & 7) + ((l & 16) >> 1)) * 128;

    for (int kcl = 0; kcl < 8; ++kcl) {
        const int kcg = ks * 8 + kcl;
        const int sect = kcg >> 2;
        const int p = sect >> 2, qq = sect & 3;
        const int ccol = (kcg & 3) * 64;
        for (int i = tid; i < 1024; i += 256) {
            const int row = i >> 3, ch = i & 7;
            const u32 dst = sw128((u32)(row * 128 + ch * 16));
            *(uint4*)(sm + dst) = *(const uint4*)(AB + (size_t)row * 4096 + kcg * 64 + ch * 8);
            const int m = blkm * 128 + row;
            const int hh = m >> 5, ww = m & 31;
            const int n = (hh * 4 + p) * WDIM + ww * 4 + qq;
            *(uint4*)(sm + 16384 + dst) = *(const uint4*)(XtB + (size_t)n * 256 + ccol + ch * 8);
        }
        __syncthreads();
        #pragma unroll
        for (int s = 0; s < 4; ++s) {
            const u32 cA = ((u32)((2 * s + ((l >> 4) & 1)) ^ (l & 7))) << 4;
            const u32 cB = ((u32)((2 * s + ((l >> 3) & 1)) ^ (l & 7))) << 4;
            u32 a[2][4], bf[4][4];
            #pragma unroll
            for (int mt = 0; mt < 2; ++mt)
                ldm_x4(a[mt], sb + rowA[mt] + cA);
            #pragma unroll
            for (int g = 0; g < 4; ++g)
                ldm_x4(bf[g], sb + 16384 + rowB[g] + cB);
            #pragma unroll
            for (int mt = 0; mt < 2; ++mt)
                #pragma unroll
                for (int g = 0; g < 4; ++g)
                    #pragma unroll
                    for (int hf = 0; hf < 2; ++hf) {
                        float* A4 = acc[mt][g * 2 + hf];
                        mma_a(A4[0], A4[1], A4[2], A4[3],
                              a[mt][0], a[mt][1], a[mt][2], a[mt][3],
                              bf[g][2 * hf], bf[g][2 * hf + 1]);
                    }
        }
        __syncthreads();
    }

    #pragma unroll
    for (int mt = 0; mt < 2; ++mt) {
        const int o = blko * 128 + wm * 32 + mt * 16 + (l >> 2);
        #pragma unroll
        for (int nt = 0; nt < 8; ++nt) {
            const int m = blkm * 128 + wo * 64 + nt * 8 + 2 * (l & 3);
            float* dst = part + ((size_t)zz * CDIM + o) * NKV + m;
            *(float2*)dst = make_float2(acc[mt][nt][0], acc[mt][nt][1]);
            *(float2*)(dst + 8 * NKV) = make_float2(acc[mt][nt][2], acc[mt][nt][3]);
        }
    }
}

// ===================== conv reduce + BN + transpose -> xrT fp16 ===============
__global__ __launch_bounds__(256) void conv_reduce_bn_T(
    const float* __restrict__ part,
    const float* __restrict__ gam, const float* __restrict__ bet,
    const float* __restrict__ mu,  const float* __restrict__ var,
    u16* __restrict__ xrT) {
    __shared__ float s[64][65];
    const int m0 = blockIdx.x * 64;
    const int o0 = blockIdx.y * 64;
    const int b  = blockIdx.z;
    const int tid = threadIdx.x;
    const int o_l0 = tid >> 4, m4 = (tid & 15) * 4;
    #pragma unroll
    for (int i = 0; i < 4; ++i) {
        const int o_l = o_l0 + i * 16;
        const int o = o0 + o_l;
        float4 sum = make_float4(0.f, 0.f, 0.f, 0.f);
        #pragma unroll
        for (int ks = 0; ks < 8; ++ks) {
            const float4 p = *(const float4*)&part[((size_t)(ks * 2 + b) * CDIM + o) * NKV + m0 + m4];
            sum.x += p.x; sum.y += p.y; sum.z += p.z; sum.w += p.w;
        }
        const float inv = gam[o] * rsqrtf(var[o] + EPSBN);
        const float mb = mu[o], be = bet[o];
        s[o_l][m4 + 0] = (sum.x - mb) * inv + be;
        s[o_l][m4 + 1] = (sum.y - mb) * inv + be;
        s[o_l][m4 + 2] = (sum.z - mb) * inv + be;
        s[o_l][m4 + 3] = (sum.w - mb) * inv + be;
    }
    __syncthreads();
    const int m_l = tid >> 2, cq = tid & 3;
    u16* orow = xrT + ((size_t)(b * NKV + m0 + m_l)) * 256 + o0;
    #pragma unroll
    for (int j = 0; j < 4; ++j) {
        const int c0 = (cq + j * 4) * 4;
        float4 v = make_float4(s[c0][m_l], s[c0 + 1][m_l],
                               s[c0 + 2][m_l], s[c0 + 3][m_l]);
        *(u64*)(orow + c0) = cvt4h(v);
    }
}

// ---------------- alpha/bias --------------------------------------------------
__global__ __launch_bounds__(256) void alpha_kernel(
    const float* __restrict__ wproj, const float* __restrict__ v,
    const float* __restrict__ gam, const float* __restrict__ bet,
    const float* __restrict__ mu,  const float* __restrict__ var,
    float* __restrict__ alpha, float* __restrict__ bias) {
    const int b = blockIdx.x;
    const int o = threadIdx.x;
    __shared__ float vs[CDIM];
    vs[o] = v[b * CDIM + o];
    __syncthreads();
    float p = 0.f;
    const float* wr = wproj + (size_t)o * CDIM;
    #pragma unroll 8
    for (int c = 0; c < CDIM; ++c) p = fmaf(wr[c], vs[c], p);
    const float inv = gam[o] * rsqrtf(var[o] + EPSBN);
    alpha[b * CDIM + o] = p * inv;
    if (b == 0) bias[o] = bet[o] - mu[o] * inv;
}

// ===================== fp16 mma.sync attention (f16 accum, kv-split) ==========
#define SM_QOFF 32768
#define SM_TOT  40960
#define NTILES  16

__global__ __launch_bounds__(256, 2)
void attn_mma(const u16* __restrict__ qbf, const u16* __restrict__ kbf,
              float* __restrict__ attn) {
    extern __shared__ char smem[];
    const u32 sb  = smem_u32(smem);
    const int tid = threadIdx.x;
    const int wid = tid >> 5, l = tid & 31;
    const int seg  = blockIdx.x;
    const int half = blockIdx.y;
    const int bh   = blockIdx.z;

    {
        const uint4* ksrc = (const uint4*)(kbf + (size_t)(bh * NKV + half * 512) * 32);
        for (int idx = tid; idx < 512 * 4; idx += 256) {
            const int row = idx >> 2, c = idx & 3;
            const u32 off = (u32)((row >> 1) * 128 + (row & 1) * 64 + c * 16);
            *(uint4*)(smem + sw128(off)) = ksrc[idx];
        }
    }
    __syncthreads();

    const int brow = (l & 7) + ((l & 16) >> 1);
    u32 baddr[2];
    #pragma unroll
    for (int s = 0; s < 2; ++s) {
        const u32 off = (u32)((brow >> 1) * 128 + (brow & 1) * 64
                              + (2 * s + ((l >> 3) & 1)) * 16);
        baddr[s] = sb + sw128(off);
    }
    const int Rr = wid * 16 + (l & 15);
    u32 aaddr[2];
    #pragma unroll
    for (int s = 0; s < 2; ++s) {
        const u32 off = (u32)((Rr >> 1) * 128 + (Rr & 1) * 64 + (2 * s + (l >> 4)) * 16);
        aaddr[s] = sb + SM_QOFF + sw128(off);
    }

    const float scale = 0.17677669529663687f;
    float* ob = attn + ((size_t)(half * 16 + bh)) * NDIM;
    const u32 NEGINF2 = 0xFC00FC00u;

    for (int t = 0; t < NTILES; ++t) {
        const int n_base = (seg * NTILES + t) * 128;
        {
            const uint4* qsrc = (const uint4*)(qbf + ((size_t)bh * NDIM + n_base) * 32);
            const int row = tid >> 1;
            const int c0 = (tid & 1) * 2;
            #pragma unroll
            for (int j = 0; j < 2; ++j) {
                const int c = c0 + j;
                const u32 off = (u32)((row >> 1) * 128 + (row & 1) * 64 + c * 16);
                *(uint4*)(smem + SM_QOFF + sw128(off)) = qsrc[(size_t)row * 4 + c];
            }
        }
        __syncwarp();

        u32 a[2][4];
        ldm_x4(a[0], aaddr[0]);
        ldm_x4(a[1], aaddr[1]);
        __syncwarp();

        u32 rm0 = NEGINF2, rm1 = NEGINF2;
        #pragma unroll 4
        for (int kv = 0; kv < 32; ++kv) {
            const u32 off = (u32)kv * 1024;
            u32 b0[4], b1[4];
            ldm_x4(b0, baddr[0] + off);
            ldm_x4(b1, baddr[1] + off);
            #pragma unroll
            for (int g = 0; g < 2; ++g) {
                u32 A0, A1, B0, B1;
                mma_h(A0, A1, a[0][0], a[0][1], a[0][2], a[0][3],
                      b0[2 * g], b0[2 * g + 1]);
                mma_h(B0, B1, a[1][0], a[1][1], a[1][2], a[1][3],
                      b1[2 * g], b1[2 * g + 1]);
                rm0 = hmax2u(rm0, hadd2u(A0, B0));
                rm1 = hmax2u(rm1, hadd2u(A1, B1));
            }
        }
        __half2 h0 = *reinterpret_cast<__half2*>(&rm0);
        __half2 h1 = *reinterpret_cast<__half2*>(&rm1);
        float rmax[2];
        rmax[0] = fmaxf(__half2float(__low2half(h0)), __half2float(__high2half(h0)));
        rmax[1] = fmaxf(__half2float(__low2half(h1)), __half2float(__high2half(h1)));
        #pragma unroll
        for (int rr = 0; rr < 2; ++rr) {
            float v = rmax[rr];
            v = fmaxf(v, __shfl_xor_sync(0xffffffffu, v, 1));
            v = fmaxf(v, __shfl_xor_sync(0xffffffffu, v, 2));
            rmax[rr] = v;
        }
        if ((l & 3) == 0) {
            const int rbase = n_base + wid * 16;
            ob[rbase + (l >> 2) + 0] = rmax[0] * scale;
            ob[rbase + (l >> 2) + 8] = rmax[1] * scale;
        }
        __syncwarp();
    }
}

// ---------------- fused tail: S = sum_h max(halves); out = alpha*S + bias -----
// grid (64 n-chunks, 2 b); 256 threads; each block: 256 n x all 256 o.
__global__ __launch_bounds__(256) void fused_tail(
    const float* __restrict__ attn, const float* __restrict__ alpha,
    const float* __restrict__ bias, float* __restrict__ out) {
    __shared__ float Ssh[256];
    __shared__ float ash[256], bsh[256];
    const int n0 = blockIdx.x * 256;
    const int b  = blockIdx.y;
    const int tid = threadIdx.x;
    // S for this n-chunk
    {
        const int n = n0 + tid;
        float s = 0.f;
        #pragma unroll
        for (int h = 0; h < NHEADS; ++h) {
            const size_t base = ((size_t)(b * NHEADS + h)) * NDIM + n;
            s += fmaxf(attn[base], attn[base + (size_t)16 * NDIM]);
        }
        Ssh[tid] = s;
        ash[tid] = alpha[b * CDIM + tid];
        bsh[tid] = bias[tid];
    }
    __syncthreads();
    // write 256 o rows x 256 n: thread handles 4 consecutive n per (o, iter)
    const int nq = (tid & 63) * 4;     // n offset within chunk
    const int o0 = tid >> 6;           // 0..3
    float4 s4 = *(const float4*)&Ssh[nq];
    #pragma unroll
    for (int i = 0; i < 64; ++i) {
        const int o = o0 + i * 4;
        const float a = ash[o], bi = bsh[o];
        float4 r;
        r.x = fmaf(a, s4.x, bi); r.y = fmaf(a, s4.y, bi);
        r.z = fmaf(a, s4.z, bi); r.w = fmaf(a, s4.w, bi);
        *(float4*)&out[((size_t)(b * CDIM + o)) * NDIM + n0 + nq] = r;
    }
}

// ===================== launch (stream-forked for graph overlap) ================
extern "C" void kernel_launch(void* const* d_in, const int* in_sizes, int n_in,
                              void* d_out, int out_size) {
    const float* x      = (const float*)d_in[0];
    const float* w_q    = (const float*)d_in[1];
    const float* w_k    = (const float*)d_in[2];
    const float* w_sr   = (const float*)d_in[3];
    const float* sr_g   = (const float*)d_in[4];
    const float* sr_b   = (const float*)d_in[5];
    const float* sr_m   = (const float*)d_in[6];
    const float* sr_v   = (const float*)d_in[7];
    const float* w_proj = (const float*)d_in[8];
    const float* pj_g   = (const float*)d_in[9];
    const float* pj_b   = (const float*)d_in[10];
    const float* pj_m   = (const float*)d_in[11];
    const float* pj_v   = (const float*)d_in[12];
    float* out = (float*)d_out;

    u16 *qbf, *kbf, *Xt, *xrT, *wqs, *wks, *wsrs;
    float *part, *attn, *vp, *v, *alpha, *bias;
    cudaGetSymbolAddress((void**)&qbf,   g_qbf);
    cudaGetSymbolAddress((void**)&kbf,   g_kbf);
    cudaGetSymbolAddress((void**)&Xt,    g_Xt);
    cudaGetSymbolAddress((void**)&xrT,   g_xrT);
    cudaGetSymbolAddress((void**)&wqs,   g_wqs);
    cudaGetSymbolAddress((void**)&wks,   g_wks);
    cudaGetSymbolAddress((void**)&wsrs,  g_wsrs);
    cudaGetSymbolAddress((void**)&part,  g_part);
    cudaGetSymbolAddress((void**)&attn,  g_attn);
    cudaGetSymbolAddress((void**)&vp,    g_vp);
    cudaGetSymbolAddress((void**)&v,     g_v);
    cudaGetSymbolAddress((void**)&alpha, g_alpha);
    cudaGetSymbolAddress((void**)&bias,  g_bias);

    cudaFuncSetAttribute(attn_mma, cudaFuncAttributeMaxDynamicSharedMemorySize, SM_TOT);
    cudaFuncSetAttribute(qgemm_mma, cudaFuncAttributeMaxDynamicSharedMemorySize, 32768);
    cudaFuncSetAttribute(convgemm_mma, cudaFuncAttributeMaxDynamicSharedMemorySize, 32768);

    cudaStream_t s1;
    cudaStreamCreateWithFlags(&s1, cudaStreamNonBlocking);
    cudaEvent_t eFork, eW, eX, eJoin;
    cudaEventCreateWithFlags(&eFork, cudaEventDisableTiming);
    cudaEventCreateWithFlags(&eW, cudaEventDisableTiming);
    cudaEventCreateWithFlags(&eX, cudaEventDisableTiming);
    cudaEventCreateWithFlags(&eJoin, cudaEventDisableTiming);

    cudaEventRecord(eFork, 0);
    cudaStreamWaitEvent(s1, eFork, 0);

    // ---- s1: weight converts (concurrent with transpose) ----
    convert_w<<<64, 256, 0, s1>>>(w_q, wqs);
    convert_w<<<64, 256, 0, s1>>>(w_k, wks);
    convert_wsr_perm<<<256, 256, 0, s1>>>(w_sr, wsrs);
    cudaEventRecord(eW, s1);

    // ---- main: the single x pass ----
    transpose_split_x<<<dim3(256, 4, 2), 256>>>(x, Xt, vp);
    cudaEventRecord(eX, 0);
    cudaStreamWaitEvent(0, eW, 0);     // main (kv-chain) needs wsrs/wks
    cudaStreamWaitEvent(s1, eX, 0);    // s1 (q-chain) needs Xt

    // ---- s1: q-chain + v/alpha ----
    qgemm_mma<<<dim3(128, 2, 2), 256, 32768, s1>>>(Xt, wqs, qbf, NDIM);
    vp_reduce<<<BSZ * CDIM, 256, 0, s1>>>(vp, v);
    alpha_kernel<<<BSZ, CDIM, 0, s1>>>(w_proj, v, pj_g, pj_b, pj_m, pj_v, alpha, bias);
    cudaEventRecord(eJoin, s1);

    // ---- main: kv-chain ----
    convgemm_mma<<<dim3(8, 2, 16), 256, 32768>>>(wsrs, Xt, part);
    conv_reduce_bn_T<<<dim3(16, 4, 2), 256>>>(part, sr_g, sr_b, sr_m, sr_v, xrT);
    qgemm_mma<<<dim3(8, 2, 2), 256, 32768>>>(xrT, wks, kbf, NKV);   // k GEMM

    // ---- join, then attention + fused tail ----
    cudaStreamWaitEvent(0, eJoin, 0);
    attn_mma<<<dim3(8, 2, 16), 256, SM_TOT>>>(qbf, kbf, attn);
    fused_tail<<<dim3(64, 2), 256>>>(attn, alpha, bias, out);
}